// round 1
// baseline (speedup 1.0000x reference)
#include <cuda_runtime.h>
#include <math.h>

#define Bn 512
#define Vn 5023
#define Fn 9976
#define Sn 100
#define En 50

// ---------------- device scratch (no allocations allowed) ----------------
__device__ float g_P[Bn][192];       // [betas(150) | pose_feature(36)] padded
__device__ float g_Arel[Bn][60];     // 5 joints x 3x4 rows
__device__ int   g_yrot[Bn];
__device__ float g_Jpart[32][2265];  // split-K partials for J_regressor contraction
__device__ float g_Jfin[2265];       // [j][c*151 + l]; l==150 -> template base

// ---------------- Rodrigues (matches reference formula exactly) ----------
__device__ __forceinline__ void rodrigues3(const float* r, float* R) {
    const float e = 1e-8f;
    float a0 = r[0] + e, a1 = r[1] + e, a2 = r[2] + e;
    float angle = sqrtf(a0*a0 + a1*a1 + a2*a2);
    float inv = 1.f / angle;
    float ax = r[0]*inv, ay = r[1]*inv, az = r[2]*inv;
    float s = sinf(angle), c = cosf(angle), t = 1.f - c;
    R[0] = 1.f - t*(ay*ay + az*az);
    R[1] = -s*az + t*ax*ay;
    R[2] =  s*ay + t*ax*az;
    R[3] =  s*az + t*ax*ay;
    R[4] = 1.f - t*(ax*ax + az*az);
    R[5] = -s*ax + t*ay*az;
    R[6] = -s*ay + t*ax*az;
    R[7] =  s*ax + t*ay*az;
    R[8] = 1.f - t*(ax*ax + ay*ay);
}

// ---------------- K1a: split-K partials of Jr @ [shapedirs|template] -----
__global__ void k_jreg_partial(const float* __restrict__ SD,
                               const float* __restrict__ tmpl,
                               const float* __restrict__ Jr) {
    __shared__ float jr_s[5][157];
    int blk = blockIdx.x;              // 0..31
    int v0 = blk * 157;
    int nv = min(157, Vn - v0);
    for (int j = 0; j < 5; j++)
        for (int i = threadIdx.x; i < nv; i += 256)
            jr_s[j][i] = Jr[j * Vn + v0 + i];
    __syncthreads();

    // each thread owns columns tid and tid+256 (453 total: c*151+l, l=150 -> template)
    float acc[2][5];
    int cc[2], ll[2];
    bool va[2];
    #pragma unroll
    for (int s2 = 0; s2 < 2; s2++) {
        int col = threadIdx.x + s2 * 256;
        va[s2] = (col < 453);
        cc[s2] = col / 151;
        ll[s2] = col - cc[s2] * 151;
        #pragma unroll
        for (int j = 0; j < 5; j++) acc[s2][j] = 0.f;
    }
    for (int v = 0; v < nv; v++) {
        float jv[5];
        #pragma unroll
        for (int j = 0; j < 5; j++) jv[j] = jr_s[j][v];
        #pragma unroll
        for (int s2 = 0; s2 < 2; s2++) {
            if (va[s2]) {
                float d = (ll[s2] < 150)
                    ? SD[(size_t)(v0 + v) * 450 + cc[s2] * 150 + ll[s2]]
                    : tmpl[(size_t)(v0 + v) * 3 + cc[s2]];
                #pragma unroll
                for (int j = 0; j < 5; j++) acc[s2][j] = fmaf(jv[j], d, acc[s2][j]);
            }
        }
    }
    #pragma unroll
    for (int s2 = 0; s2 < 2; s2++)
        if (va[s2]) {
            int col = threadIdx.x + s2 * 256;
            #pragma unroll
            for (int j = 0; j < 5; j++) g_Jpart[blk][j * 453 + col] = acc[s2][j];
        }
}

// ---------------- K1b: fixed-order reduction (deterministic) -------------
__global__ void k_jreg_reduce() {
    int idx = blockIdx.x * blockDim.x + threadIdx.x;
    if (idx < 2265) {
        float s = 0.f;
        #pragma unroll 8
        for (int k = 0; k < 32; k++) s += g_Jpart[k][idx];
        g_Jfin[idx] = s;
    }
}

// ---------------- K2: per-batch pose / joints / chain / A_rel / y_rot ----
__global__ void k_batch(const float* __restrict__ shp, const float* __restrict__ ex,
                        const float* __restrict__ pose, const float* __restrict__ eye) {
    int b = blockIdx.x * blockDim.x + threadIdx.x;
    if (b >= Bn) return;

    float fp[15];
    fp[0] = pose[b*6+0]; fp[1] = pose[b*6+1]; fp[2] = pose[b*6+2];
    fp[3] = 0.f; fp[4] = 0.f; fp[5] = 0.f;
    fp[6] = pose[b*6+3]; fp[7] = pose[b*6+4]; fp[8] = pose[b*6+5];
    #pragma unroll
    for (int i = 0; i < 6; i++) fp[9+i] = eye[b*6+i];

    float R[5][9];
    #pragma unroll
    for (int j = 0; j < 5; j++) rodrigues3(&fp[3*j], R[j]);

    // joints = Jbase + betas @ Jshape  (all threads read same g_Jfin -> broadcast)
    float joints[5][3];
    #pragma unroll
    for (int j = 0; j < 5; j++)
        #pragma unroll
        for (int c = 0; c < 3; c++)
            joints[j][c] = g_Jfin[j*453 + c*151 + 150];
    for (int l = 0; l < 150; l++) {
        float beta = (l < 100) ? shp[b*100 + l] : ex[b*50 + (l - 100)];
        g_P[b][l] = beta;
        #pragma unroll
        for (int j = 0; j < 5; j++)
            #pragma unroll
            for (int c = 0; c < 3; c++)
                joints[j][c] = fmaf(beta, g_Jfin[j*453 + c*151 + l], joints[j][c]);
    }

    // pose feature (rot_mats[1:] - I)
    for (int j = 1; j < 5; j++)
        #pragma unroll
        for (int e = 0; e < 9; e++)
            g_P[b][150 + (j-1)*9 + e] = R[j][e] - ((e == 0 || e == 4 || e == 8) ? 1.f : 0.f);

    const int par[5] = {-1, 0, 1, 1, 1};
    float relJ[5][3];
    #pragma unroll
    for (int c = 0; c < 3; c++) relJ[0][c] = joints[0][c];
    for (int j = 1; j < 5; j++)
        #pragma unroll
        for (int c = 0; c < 3; c++) relJ[j][c] = joints[j][c] - joints[par[j]][c];

    float GR[5][9], Gt[5][3];
    #pragma unroll
    for (int e2 = 0; e2 < 9; e2++) GR[0][e2] = R[0][e2];
    #pragma unroll
    for (int c = 0; c < 3; c++) Gt[0][c] = relJ[0][c];
    for (int j = 1; j < 5; j++) {
        int p = par[j];
        for (int m = 0; m < 3; m++) {
            for (int n = 0; n < 3; n++)
                GR[j][m*3+n] = GR[p][m*3+0]*R[j][0*3+n] + GR[p][m*3+1]*R[j][1*3+n]
                             + GR[p][m*3+2]*R[j][2*3+n];
            Gt[j][m] = GR[p][m*3+0]*relJ[j][0] + GR[p][m*3+1]*relJ[j][1]
                     + GR[p][m*3+2]*relJ[j][2] + Gt[p][m];
        }
    }
    for (int j = 0; j < 5; j++) {
        for (int m = 0; m < 3; m++) {
            float tr = Gt[j][m] - (GR[j][m*3+0]*joints[j][0] + GR[j][m*3+1]*joints[j][1]
                                 + GR[j][m*3+2]*joints[j][2]);
            g_Arel[b][j*12 + m*4 + 0] = GR[j][m*3+0];
            g_Arel[b][j*12 + m*4 + 1] = GR[j][m*3+1];
            g_Arel[b][j*12 + m*4 + 2] = GR[j][m*3+2];
            g_Arel[b][j*12 + m*4 + 3] = tr;
        }
    }

    // y_rot bucket: rel = R[global] @ R[neck]; need column 0
    float r00 = R[0][0]*R[1][0] + R[0][1]*R[1][3] + R[0][2]*R[1][6];
    float r10 = R[0][3]*R[1][0] + R[0][4]*R[1][3] + R[0][5]*R[1][6];
    float r20 = R[0][6]*R[1][0] + R[0][7]*R[1][3] + R[0][8]*R[1][6];
    float sy = sqrtf(r00*r00 + r10*r10);
    float ydeg = atan2f(-r20, sy) * 57.29577951308232087f;
    int yr = (int)rintf(fminf(ydeg, 39.f));
    if (yr < 0) yr = (yr < -39) ? 78 : (39 - yr);
    g_yrot[b] = yr;
}

// ---------------- K3: fused shape+pose GEMM + LBS ------------------------
// tile: 128 batches x 16 vertices; 256 threads; thread = 8 batches x 1 vertex
// smem strides 187 / 61 / 564 are odd-mod-32 -> conflict-free LDS
#define SMEM_FLOATS (128*187 + 16*564 + 128*61 + 80 + 48)

__global__ __launch_bounds__(256, 1)
void k_main(const float* __restrict__ SD, const float* __restrict__ PD,
            const float* __restrict__ tmpl, const float* __restrict__ W,
            float* __restrict__ out) {
    extern __shared__ float sm[];
    float* P_s = sm;                    // [128][187]
    float* D_s = sm + 128*187;          // [16][3][188]
    float* A_s = D_s + 16*564;          // [128][61] (60 used)
    float* w_s = A_s + 128*61;          // [16][5]
    float* t_s = w_s + 80;              // [16][3]

    const int tid = threadIdx.x;
    const int warp = tid >> 5, lane = tid & 31;
    const int v0 = blockIdx.x * 16;
    const int b0 = blockIdx.y * 128;

    for (int r = warp; r < 128; r += 8) {
        const float* src = g_P[b0 + r];
        for (int l = lane; l < 186; l += 32)
            P_s[r*187 + l] = src[l];
    }
    for (int vi = warp; vi < 16; vi += 8) {
        int v = v0 + vi;
        if (v < Vn) {
            const float* src = SD + (size_t)v * 450;
            for (int idx = lane; idx < 450; idx += 32) {
                int c = idx / 150, l = idx - c*150;
                D_s[(vi*3 + c)*188 + l] = src[idx];
            }
        } else {
            for (int idx = lane; idx < 450; idx += 32) {
                int c = idx / 150, l = idx - c*150;
                D_s[(vi*3 + c)*188 + l] = 0.f;
            }
        }
    }
    for (int k = warp; k < 36; k += 8) {
        for (int idx = lane; idx < 48; idx += 32) {
            int vi = idx / 3, c = idx - vi*3;
            int v = v0 + vi;
            D_s[(vi*3 + c)*188 + 150 + k] =
                (v < Vn) ? PD[(size_t)k * (Vn*3) + (size_t)v*3 + c] : 0.f;
        }
    }
    for (int idx = tid; idx < 128*60; idx += 256) {
        int r = idx / 60, q = idx - r*60;
        A_s[r*61 + q] = g_Arel[b0 + r][q];
    }
    if (tid < 80) {
        int vi = tid / 5, j = tid - vi*5;
        int v = v0 + vi;
        w_s[tid] = (v < Vn) ? W[(size_t)v*5 + j] : 0.f;
    }
    if (tid < 48) {
        int vi = tid / 3, c = tid - vi*3;
        int v = v0 + vi;
        t_s[tid] = (v < Vn) ? tmpl[(size_t)v*3 + c] : 0.f;
    }
    __syncthreads();

    const int b_base = tid & 15;
    const int vi = tid >> 4;
    const float* Dv = D_s + vi * 564;
    const float* Pb = P_s + b_base * 187;

    float acc[8][3];
    #pragma unroll
    for (int i = 0; i < 8; i++) { acc[i][0] = 0.f; acc[i][1] = 0.f; acc[i][2] = 0.f; }

    #pragma unroll 2
    for (int l = 0; l < 186; l++) {
        float d0 = Dv[l], d1 = Dv[188 + l], d2 = Dv[376 + l];
        #pragma unroll
        for (int i = 0; i < 8; i++) {
            float p = Pb[i * (16*187) + l];
            acc[i][0] = fmaf(p, d0, acc[i][0]);
            acc[i][1] = fmaf(p, d1, acc[i][1]);
            acc[i][2] = fmaf(p, d2, acc[i][2]);
        }
    }

    int v = v0 + vi;
    if (v >= Vn) return;
    float w0 = w_s[vi*5+0], w1 = w_s[vi*5+1], w2 = w_s[vi*5+2],
          w3 = w_s[vi*5+3], w4 = w_s[vi*5+4];
    float tx = t_s[vi*3+0], ty = t_s[vi*3+1], tz = t_s[vi*3+2];

    #pragma unroll
    for (int i = 0; i < 8; i++) {
        int bb = b_base + i*16;
        const float* Ar = A_s + bb*61;
        float T[12];
        #pragma unroll
        for (int r = 0; r < 12; r++)
            T[r] = fmaf(w0, Ar[r],
                   fmaf(w1, Ar[12+r],
                   fmaf(w2, Ar[24+r],
                   fmaf(w3, Ar[36+r], w4 * Ar[48+r]))));
        float vx = tx + acc[i][0], vy = ty + acc[i][1], vz = tz + acc[i][2];
        float ox = fmaf(T[0], vx, fmaf(T[1], vy, fmaf(T[2],  vz, T[3])));
        float oy = fmaf(T[4], vx, fmaf(T[5], vy, fmaf(T[6],  vz, T[7])));
        float oz = fmaf(T[8], vx, fmaf(T[9], vy, fmaf(T[10], vz, T[11])));
        size_t o = ((size_t)(b0 + bb) * Vn + v) * 3;
        out[o+0] = ox; out[o+1] = oy; out[o+2] = oz;
    }
}

// ---------------- K4: landmarks ------------------------------------------
__global__ void k_lmk(const int* __restrict__ faces,
                      const int* __restrict__ sfi, const float* __restrict__ sbc,
                      const int* __restrict__ dfi, const float* __restrict__ dbc,
                      const int* __restrict__ ffi, const float* __restrict__ fbc,
                      float* __restrict__ out) {
    int b = blockIdx.x;
    int t = threadIdx.x;
    if (t >= 136) return;
    const size_t V3  = (size_t)Vn * 3;
    const size_t lm2 = (size_t)Bn * V3;
    const size_t lm3 = lm2 + (size_t)Bn * 68 * 3;

    int face; float w0, w1, w2; size_t ob;
    if (t < 68) {
        face = ffi[t]; w0 = fbc[t*3]; w1 = fbc[t*3+1]; w2 = fbc[t*3+2];
        ob = lm3 + ((size_t)b * 68 + t) * 3;
    } else {
        int lj = t - 68;
        if (lj < 17) {
            int q = g_yrot[b] * 17 + lj;
            face = dfi[q]; w0 = dbc[q*3]; w1 = dbc[q*3+1]; w2 = dbc[q*3+2];
        } else {
            int q = lj - 17;
            face = sfi[q]; w0 = sbc[q*3]; w1 = sbc[q*3+1]; w2 = sbc[q*3+2];
        }
        ob = lm2 + ((size_t)b * 68 + lj) * 3;
    }
    int f0 = faces[face*3+0], f1 = faces[face*3+1], f2 = faces[face*3+2];
    const float* vb = out + (size_t)b * V3;
    #pragma unroll
    for (int c = 0; c < 3; c++)
        out[ob + c] = w0 * vb[(size_t)f0*3 + c]
                    + w1 * vb[(size_t)f1*3 + c]
                    + w2 * vb[(size_t)f2*3 + c];
}

// ---------------- launch --------------------------------------------------
extern "C" void kernel_launch(void* const* d_in, const int* in_sizes, int n_in,
                              void* d_out, int out_size) {
    const float* shape   = (const float*)d_in[0];
    const float* expr    = (const float*)d_in[1];
    const float* pose    = (const float*)d_in[2];
    const float* eyep    = (const float*)d_in[3];
    const float* tmpl    = (const float*)d_in[4];
    const float* SD      = (const float*)d_in[5];
    const float* PD      = (const float*)d_in[6];
    const float* Jr      = (const float*)d_in[7];
    const float* W       = (const float*)d_in[8];
    const int*   faces   = (const int*)  d_in[9];
    const int*   sfi     = (const int*)  d_in[10];
    const float* sbc     = (const float*)d_in[11];
    const int*   dfi     = (const int*)  d_in[12];
    const float* dbc     = (const float*)d_in[13];
    const int*   ffi     = (const int*)  d_in[14];
    const float* fbc     = (const float*)d_in[15];
    float* out = (float*)d_out;

    k_jreg_partial<<<32, 256>>>(SD, tmpl, Jr);
    k_jreg_reduce<<<9, 256>>>();
    k_batch<<<2, 256>>>(shape, expr, pose, eyep);

    const int smem_bytes = SMEM_FLOATS * 4;
    cudaFuncSetAttribute(k_main, cudaFuncAttributeMaxDynamicSharedMemorySize, smem_bytes);
    k_main<<<dim3((Vn + 15) / 16, Bn / 128), 256, smem_bytes>>>(SD, PD, tmpl, W, out);

    k_lmk<<<Bn, 160>>>(faces, sfi, sbc, dfi, dbc, ffi, fbc, out);
}

// round 3
// speedup vs baseline: 1.8139x; 1.8139x over previous
#include <cuda_runtime.h>
#include <math.h>
#include <stdint.h>

#define Bn 512
#define Vn 5023
#define Fn 9976

typedef unsigned long long ull;

// ---------------- device scratch ----------------
__device__ float g_P[Bn][192];       // [betas(150) | pose_feature(36)] zero-padded to 192
__device__ float g_Arel[Bn][60];
__device__ int   g_yrot[Bn];
__device__ float g_Jpart[157][2272];
__device__ float g_Jfin[2272];       // [j][c*151 + l]; l==150 -> template base

// ---------------- helpers ----------------
#define CMP(v,i) ((i)==0?(v).x:((i)==1?(v).y:((i)==2?(v).z:(v).w)))

__device__ __forceinline__ uint32_t smem_u32(const void* p) {
    return (uint32_t)__cvta_generic_to_shared(p);
}
#define FMA2(acc, a, b) \
    asm("fma.rn.f32x2 %0, %1, %2, %0;" : "+l"(acc) : "l"(a), "l"(b))
#define PACK2(dd, f) \
    asm("mov.b64 %0, {%1, %1};" : "=l"(dd) : "r"(__float_as_uint(f)))
#define UNPK(lo, hi, a) \
    asm("mov.b64 {%0, %1}, %2;" : "=r"(lo), "=r"(hi) : "l"(a))

__device__ __forceinline__ void rodrigues3(const float* r, float* R) {
    const float e = 1e-8f;
    float a0 = r[0] + e, a1 = r[1] + e, a2 = r[2] + e;
    float angle = sqrtf(a0*a0 + a1*a1 + a2*a2);
    float inv = 1.f / angle;
    float ax = r[0]*inv, ay = r[1]*inv, az = r[2]*inv;
    float s = sinf(angle), c = cosf(angle), t = 1.f - c;
    R[0] = 1.f - t*(ay*ay + az*az);
    R[1] = -s*az + t*ax*ay;
    R[2] =  s*ay + t*ax*az;
    R[3] =  s*az + t*ax*ay;
    R[4] = 1.f - t*(ax*ax + az*az);
    R[5] = -s*ax + t*ay*az;
    R[6] = -s*ay + t*ax*az;
    R[7] =  s*ax + t*ay*az;
    R[8] = 1.f - t*(ax*ax + ay*ay);
}

// ---------------- K1a: split-K partials of Jr @ [shapedirs|template] -----
__global__ void k_jreg_partial(const float* __restrict__ SD,
                               const float* __restrict__ tmpl,
                               const float* __restrict__ Jr) {
    __shared__ float jr_s[5][33];
    int blk = blockIdx.x;              // 0..156
    int v0 = blk * 32;
    int nv = min(32, Vn - v0);
    if (threadIdx.x < 160) {
        int j = threadIdx.x >> 5, i = threadIdx.x & 31;
        jr_s[j][i] = (i < nv) ? Jr[j * Vn + v0 + i] : 0.f;
    }
    __syncthreads();

    float acc[2][5];
    int cc[2], ll[2]; bool va[2];
    #pragma unroll
    for (int s2 = 0; s2 < 2; s2++) {
        int col = threadIdx.x + s2 * 256;
        va[s2] = (col < 453);
        cc[s2] = col / 151; ll[s2] = col - cc[s2] * 151;
        #pragma unroll
        for (int j = 0; j < 5; j++) acc[s2][j] = 0.f;
    }
    for (int v = 0; v < nv; v++) {
        float jv[5];
        #pragma unroll
        for (int j = 0; j < 5; j++) jv[j] = jr_s[j][v];
        #pragma unroll
        for (int s2 = 0; s2 < 2; s2++) {
            if (va[s2]) {
                float d = (ll[s2] < 150)
                    ? SD[(size_t)(v0 + v) * 450 + cc[s2] * 150 + ll[s2]]
                    : tmpl[(size_t)(v0 + v) * 3 + cc[s2]];
                #pragma unroll
                for (int j = 0; j < 5; j++) acc[s2][j] = fmaf(jv[j], d, acc[s2][j]);
            }
        }
    }
    #pragma unroll
    for (int s2 = 0; s2 < 2; s2++)
        if (va[s2]) {
            int col = threadIdx.x + s2 * 256;
            #pragma unroll
            for (int j = 0; j < 5; j++) g_Jpart[blk][j * 453 + col] = acc[s2][j];
        }
}

__global__ void k_jreg_reduce() {
    int idx = blockIdx.x * blockDim.x + threadIdx.x;
    if (idx < 2265) {
        float s = 0.f;
        for (int k = 0; k < 157; k++) s += g_Jpart[k][idx];
        g_Jfin[idx] = s;
    }
}

// ---------------- K2: per-batch pose / joints / chain / A_rel / y_rot ----
__global__ void k_batch(const float* __restrict__ shp, const float* __restrict__ ex,
                        const float* __restrict__ pose, const float* __restrict__ eye) {
    int b = blockIdx.x * blockDim.x + threadIdx.x;
    if (b >= Bn) return;

    float fp[15];
    fp[0] = pose[b*6+0]; fp[1] = pose[b*6+1]; fp[2] = pose[b*6+2];
    fp[3] = 0.f; fp[4] = 0.f; fp[5] = 0.f;
    fp[6] = pose[b*6+3]; fp[7] = pose[b*6+4]; fp[8] = pose[b*6+5];
    #pragma unroll
    for (int i = 0; i < 6; i++) fp[9+i] = eye[b*6+i];

    float R[5][9];
    #pragma unroll
    for (int j = 0; j < 5; j++) rodrigues3(&fp[3*j], R[j]);

    float joints[5][3];
    #pragma unroll
    for (int j = 0; j < 5; j++)
        #pragma unroll
        for (int c = 0; c < 3; c++)
            joints[j][c] = g_Jfin[j*453 + c*151 + 150];
    for (int l = 0; l < 150; l++) {
        float beta = (l < 100) ? shp[b*100 + l] : ex[b*50 + (l - 100)];
        g_P[b][l] = beta;
        #pragma unroll
        for (int j = 0; j < 5; j++)
            #pragma unroll
            for (int c = 0; c < 3; c++)
                joints[j][c] = fmaf(beta, g_Jfin[j*453 + c*151 + l], joints[j][c]);
    }
    for (int j = 1; j < 5; j++)
        #pragma unroll
        for (int e = 0; e < 9; e++)
            g_P[b][150 + (j-1)*9 + e] = R[j][e] - ((e == 0 || e == 4 || e == 8) ? 1.f : 0.f);

    const int par[5] = {-1, 0, 1, 1, 1};
    float relJ[5][3];
    #pragma unroll
    for (int c = 0; c < 3; c++) relJ[0][c] = joints[0][c];
    for (int j = 1; j < 5; j++)
        #pragma unroll
        for (int c = 0; c < 3; c++) relJ[j][c] = joints[j][c] - joints[par[j]][c];

    float GR[5][9], Gt[5][3];
    #pragma unroll
    for (int e2 = 0; e2 < 9; e2++) GR[0][e2] = R[0][e2];
    #pragma unroll
    for (int c = 0; c < 3; c++) Gt[0][c] = relJ[0][c];
    for (int j = 1; j < 5; j++) {
        int p = par[j];
        for (int m = 0; m < 3; m++) {
            for (int n = 0; n < 3; n++)
                GR[j][m*3+n] = GR[p][m*3+0]*R[j][0*3+n] + GR[p][m*3+1]*R[j][1*3+n]
                             + GR[p][m*3+2]*R[j][2*3+n];
            Gt[j][m] = GR[p][m*3+0]*relJ[j][0] + GR[p][m*3+1]*relJ[j][1]
                     + GR[p][m*3+2]*relJ[j][2] + Gt[p][m];
        }
    }
    for (int j = 0; j < 5; j++)
        for (int m = 0; m < 3; m++) {
            float tr = Gt[j][m] - (GR[j][m*3+0]*joints[j][0] + GR[j][m*3+1]*joints[j][1]
                                 + GR[j][m*3+2]*joints[j][2]);
            g_Arel[b][j*12 + m*4 + 0] = GR[j][m*3+0];
            g_Arel[b][j*12 + m*4 + 1] = GR[j][m*3+1];
            g_Arel[b][j*12 + m*4 + 2] = GR[j][m*3+2];
            g_Arel[b][j*12 + m*4 + 3] = tr;
        }

    float r00 = R[0][0]*R[1][0] + R[0][1]*R[1][3] + R[0][2]*R[1][6];
    float r10 = R[0][3]*R[1][0] + R[0][4]*R[1][3] + R[0][5]*R[1][6];
    float r20 = R[0][6]*R[1][0] + R[0][7]*R[1][3] + R[0][8]*R[1][6];
    float sy = sqrtf(r00*r00 + r10*r10);
    float ydeg = atan2f(-r20, sy) * 57.29577951308232087f;
    int yr = (int)rintf(fminf(ydeg, 39.f));
    if (yr < 0) yr = (yr < -39) ? 78 : (39 - yr);
    g_yrot[b] = yr;
}

// ---------------- K3: fused shape+pose GEMM + LBS (f32x2) ----------------
// tile: 128 batches x 32 vertices; 512 threads; thread = 8 batches x 1 vertex
// P_s: [188][128] K-major, XOR bank-swizzled:  addr(l,b=bq*4+r) =
//   l*128 + G(bq,l)*4 + r,  G(bq,l) = (bq&24) | ((bq^l)&7)
// D_s: [32][3][188] rows (l-major), A_s: [128][61]
#define P_FLOATS (188*128)
#define D_FLOATS (32*3*188)
#define A_FLOATS (128*61)
#define SMEM_FLOATS (P_FLOATS + D_FLOATS + A_FLOATS + 160 + 96)

__global__ __launch_bounds__(512, 1)
void k_main(const float* __restrict__ SD, const float* __restrict__ PD,
            const float* __restrict__ tmpl, const float* __restrict__ W,
            float* __restrict__ out) {
    extern __shared__ float sm[];
    float* P_s = sm;
    float* D_s = sm + P_FLOATS;
    float* A_s = D_s + D_FLOATS;
    float* w_s = A_s + A_FLOATS;
    float* t_s = w_s + 160;

    const int tid = threadIdx.x;
    const int warp = tid >> 5, lane = tid & 31;
    const int v0 = blockIdx.x * 32;
    const int b0 = blockIdx.y * 128;

    // ---- P transpose: g_P[b][l] -> P_s[l][b] via 4x4 register tiles ----
    for (int tile = tid; tile < 47*32; tile += 512) {
        int bq = tile & 31, lblk = tile >> 5;      // l = lblk*4+j2 <= 187
        int bb = b0 + bq*4;
        float4 r0 = ((const float4*)g_P[bb+0])[lblk];
        float4 r1 = ((const float4*)g_P[bb+1])[lblk];
        float4 r2 = ((const float4*)g_P[bb+2])[lblk];
        float4 r3 = ((const float4*)g_P[bb+3])[lblk];
        #pragma unroll
        for (int j2 = 0; j2 < 4; j2++) {
            int l = lblk*4 + j2;
            int G = (bq & 24) | ((bq ^ l) & 7);
            *(float4*)(P_s + l*128 + G*4) =
                make_float4(CMP(r0,j2), CMP(r1,j2), CMP(r2,j2), CMP(r3,j2));
        }
    }
    // ---- D: shapedirs rows ----
    for (int vi = warp; vi < 32; vi += 16) {
        int v = v0 + vi;
        const float* src = SD + (size_t)v * 450;
        for (int idx = lane; idx < 450; idx += 32) {
            int c = idx / 150, l = idx - c*150;
            D_s[(vi*3 + c)*188 + l] = (v < Vn) ? src[idx] : 0.f;
        }
    }
    // ---- D: posedirs rows ----
    for (int t = tid; t < 36*96; t += 512) {
        int k = t / 96, r = t - k*96;
        int vi = r / 3, c = r - vi*3;
        int v = v0 + vi;
        D_s[(vi*3 + c)*188 + 150 + k] =
            (v < Vn) ? PD[(size_t)k * (Vn*3) + (size_t)v*3 + c] : 0.f;
    }
    // ---- A, w, t ----
    for (int t = tid; t < 128*60; t += 512) {
        int r = t / 60, q = t - r*60;
        A_s[r*61 + q] = g_Arel[b0 + r][q];
    }
    if (tid < 160) {
        int vi = tid / 5, j = tid - vi*5;
        int v = v0 + vi;
        w_s[tid] = (v < Vn) ? W[(size_t)v*5 + j] : 0.f;
    }
    if (tid < 96) {
        int vi = tid / 3, c = tid - vi*3;
        int v = v0 + vi;
        t_s[tid] = (v < Vn) ? tmpl[(size_t)v*3 + c] : 0.f;
    }
    __syncthreads();

    const int bg = tid & 15;
    const int vi = tid >> 4;
    const float* Dv = D_s + vi * 564;

    uint32_t pbase = smem_u32(P_s);
    uint32_t aA[8];
    #pragma unroll
    for (int u = 0; u < 8; u++) {
        int G = (bg & 8) | ((bg & 7) ^ u);
        aA[u] = pbase + (uint32_t)(u*128 + G*4) * 4u;
    }

    ull acc[12];
    #pragma unroll
    for (int i = 0; i < 12; i++) acc[i] = 0ull;

    #pragma unroll 1
    for (int l0 = 0; l0 < 184; l0 += 8) {
        float4 dq[2][3];
        #pragma unroll
        for (int h = 0; h < 2; h++)
            #pragma unroll
            for (int c = 0; c < 3; c++)
                dq[h][c] = *(const float4*)(Dv + c*188 + l0 + h*4);
        #pragma unroll
        for (int u = 0; u < 8; u++) {
            ull pa0, pa1, pb0, pb1;
            asm volatile("ld.shared.v2.u64 {%0,%1},[%2];"
                         : "=l"(pa0), "=l"(pa1) : "r"(aA[u]));
            asm volatile("ld.shared.v2.u64 {%0,%1},[%2+256];"
                         : "=l"(pb0), "=l"(pb1) : "r"(aA[u]));
            ull dd0, dd1, dd2;
            PACK2(dd0, CMP(dq[u>>2][0], u&3));
            PACK2(dd1, CMP(dq[u>>2][1], u&3));
            PACK2(dd2, CMP(dq[u>>2][2], u&3));
            FMA2(acc[0], pa0, dd0); FMA2(acc[1],  pa0, dd1); FMA2(acc[2],  pa0, dd2);
            FMA2(acc[3], pa1, dd0); FMA2(acc[4],  pa1, dd1); FMA2(acc[5],  pa1, dd2);
            FMA2(acc[6], pb0, dd0); FMA2(acc[7],  pb0, dd1); FMA2(acc[8],  pb0, dd2);
            FMA2(acc[9], pb1, dd0); FMA2(acc[10], pb1, dd1); FMA2(acc[11], pb1, dd2);
        }
        #pragma unroll
        for (int u = 0; u < 8; u++) aA[u] += 4096u;
    }
    {   // remainder: l = 184 (u=0), 185 (u=1)
        float4 dq0[3];
        #pragma unroll
        for (int c = 0; c < 3; c++)
            dq0[c] = *(const float4*)(Dv + c*188 + 184);
        #pragma unroll
        for (int u = 0; u < 2; u++) {
            ull pa0, pa1, pb0, pb1;
            asm volatile("ld.shared.v2.u64 {%0,%1},[%2];"
                         : "=l"(pa0), "=l"(pa1) : "r"(aA[u]));
            asm volatile("ld.shared.v2.u64 {%0,%1},[%2+256];"
                         : "=l"(pb0), "=l"(pb1) : "r"(aA[u]));
            ull dd0, dd1, dd2;
            PACK2(dd0, CMP(dq0[0], u));
            PACK2(dd1, CMP(dq0[1], u));
            PACK2(dd2, CMP(dq0[2], u));
            FMA2(acc[0], pa0, dd0); FMA2(acc[1],  pa0, dd1); FMA2(acc[2],  pa0, dd2);
            FMA2(acc[3], pa1, dd0); FMA2(acc[4],  pa1, dd1); FMA2(acc[5],  pa1, dd2);
            FMA2(acc[6], pb0, dd0); FMA2(acc[7],  pb0, dd1); FMA2(acc[8],  pb0, dd2);
            FMA2(acc[9], pb1, dd0); FMA2(acc[10], pb1, dd1); FMA2(acc[11], pb1, dd2);
        }
    }

    // ---- epilogue: LBS ----
    int v = v0 + vi;
    float af[12][2];
    #pragma unroll
    for (int i = 0; i < 12; i++) {
        uint32_t lo, hi;
        UNPK(lo, hi, acc[i]);
        af[i][0] = __uint_as_float(lo);
        af[i][1] = __uint_as_float(hi);
    }
    float w0 = w_s[vi*5+0], w1 = w_s[vi*5+1], w2 = w_s[vi*5+2],
          w3 = w_s[vi*5+3], w4 = w_s[vi*5+4];
    float tx = t_s[vi*3+0], ty = t_s[vi*3+1], tz = t_s[vi*3+2];

    #pragma unroll
    for (int j = 0; j < 8; j++) {
        int p = j >> 1, h = j & 1;
        int bb = (j < 4) ? (bg*4 + j) : (64 + bg*4 + (j - 4));
        const float* Ar = A_s + bb*61;
        float T[12];
        #pragma unroll
        for (int r = 0; r < 12; r++)
            T[r] = fmaf(w0, Ar[r],
                   fmaf(w1, Ar[12+r],
                   fmaf(w2, Ar[24+r],
                   fmaf(w3, Ar[36+r], w4 * Ar[48+r]))));
        float vx = tx + af[p*3+0][h];
        float vy = ty + af[p*3+1][h];
        float vz = tz + af[p*3+2][h];
        float ox = fmaf(T[0], vx, fmaf(T[1], vy, fmaf(T[2],  vz, T[3])));
        float oy = fmaf(T[4], vx, fmaf(T[5], vy, fmaf(T[6],  vz, T[7])));
        float oz = fmaf(T[8], vx, fmaf(T[9], vy, fmaf(T[10], vz, T[11])));
        if (v < Vn) {
            size_t o = ((size_t)(b0 + bb) * Vn + v) * 3;
            out[o+0] = ox; out[o+1] = oy; out[o+2] = oz;
        }
    }
}

// ---------------- K4: landmarks ------------------------------------------
__global__ void k_lmk(const int* __restrict__ faces,
                      const int* __restrict__ sfi, const float* __restrict__ sbc,
                      const int* __restrict__ dfi, const float* __restrict__ dbc,
                      const int* __restrict__ ffi, const float* __restrict__ fbc,
                      float* __restrict__ out) {
    int b = blockIdx.x;
    int t = threadIdx.x;
    if (t >= 136) return;
    const size_t V3  = (size_t)Vn * 3;
    const size_t lm2 = (size_t)Bn * V3;
    const size_t lm3 = lm2 + (size_t)Bn * 68 * 3;

    int face; float w0, w1, w2; size_t ob;
    if (t < 68) {
        face = ffi[t]; w0 = fbc[t*3]; w1 = fbc[t*3+1]; w2 = fbc[t*3+2];
        ob = lm3 + ((size_t)b * 68 + t) * 3;
    } else {
        int lj = t - 68;
        if (lj < 17) {
            int q = g_yrot[b] * 17 + lj;
            face = dfi[q]; w0 = dbc[q*3]; w1 = dbc[q*3+1]; w2 = dbc[q*3+2];
        } else {
            int q = lj - 17;
            face = sfi[q]; w0 = sbc[q*3]; w1 = sbc[q*3+1]; w2 = sbc[q*3+2];
        }
        ob = lm2 + ((size_t)b * 68 + lj) * 3;
    }
    int f0 = faces[face*3+0], f1 = faces[face*3+1], f2 = faces[face*3+2];
    const float* vb = out + (size_t)b * V3;
    #pragma unroll
    for (int c = 0; c < 3; c++)
        out[ob + c] = w0 * vb[(size_t)f0*3 + c]
                    + w1 * vb[(size_t)f1*3 + c]
                    + w2 * vb[(size_t)f2*3 + c];
}

// ---------------- launch --------------------------------------------------
extern "C" void kernel_launch(void* const* d_in, const int* in_sizes, int n_in,
                              void* d_out, int out_size) {
    const float* shape   = (const float*)d_in[0];
    const float* expr    = (const float*)d_in[1];
    const float* pose    = (const float*)d_in[2];
    const float* eyep    = (const float*)d_in[3];
    const float* tmpl    = (const float*)d_in[4];
    const float* SD      = (const float*)d_in[5];
    const float* PD      = (const float*)d_in[6];
    const float* Jr      = (const float*)d_in[7];
    const float* W       = (const float*)d_in[8];
    const int*   faces   = (const int*)  d_in[9];
    const int*   sfi     = (const int*)  d_in[10];
    const float* sbc     = (const float*)d_in[11];
    const int*   dfi     = (const int*)  d_in[12];
    const float* dbc     = (const float*)d_in[13];
    const int*   ffi     = (const int*)  d_in[14];
    const float* fbc     = (const float*)d_in[15];
    float* out = (float*)d_out;

    k_jreg_partial<<<157, 256>>>(SD, tmpl, Jr);
    k_jreg_reduce<<<9, 256>>>();
    k_batch<<<2, 256>>>(shape, expr, pose, eyep);

    const int smem_bytes = SMEM_FLOATS * 4;
    cudaFuncSetAttribute(k_main, cudaFuncAttributeMaxDynamicSharedMemorySize, smem_bytes);
    k_main<<<dim3(157, 4), 512, smem_bytes>>>(SD, PD, tmpl, W, out);

    k_lmk<<<Bn, 160>>>(faces, sfi, sbc, dfi, dbc, ffi, fbc, out);
}